// round 1
// baseline (speedup 1.0000x reference)
#include <cuda_runtime.h>

// Problem constants (fixed by the reference)
#define NN        64
#define INV_DX    63.0f                 // 1/DX, DX = 1/(64-1)
#define DXC       (1.0f/63.0f)
#define E_OUT_C   80.0f                 // E_IN = 1
#define FOUR_PI_F 12.566370614359172f
#define EPSF      1.1920928955078125e-07f  // float32 machine eps
#define TPB       256
#define MAXQ      512                   // NQ = 200; shared staging capacity
#define MAX_BLOCKS 2048

__device__ float g_partials[MAX_BLOCKS];

__global__ void boundary_loss_kernel(const float* __restrict__ outf,    // (2,1,64,64,64)
                                     const float* __restrict__ q,      // (NQ)
                                     const float* __restrict__ xq,     // (NQ,3)
                                     const int*   __restrict__ xi,
                                     const int*   __restrict__ yi,
                                     const int*   __restrict__ zi,
                                     const float* __restrict__ normals,// (NB,3)
                                     int nb, int nq)
{
    __shared__ float sq[MAXQ];
    __shared__ float sx[MAXQ], sy[MAXQ], sz[MAXQ];
    int nqs = (nq <= MAXQ) ? nq : MAXQ;
    for (int j = threadIdx.x; j < nqs; j += TPB) {
        sq[j] = q[j];
        sx[j] = xq[3*j + 0];
        sy[j] = xq[3*j + 1];
        sz[j] = xq[3*j + 2];
    }
    __syncthreads();

    int i = blockIdx.x * TPB + threadIdx.x;
    float acc = 0.0f;
    if (i < nb) {
        int x = xi[i], y = yi[i], z = zi[i];
        float px = x * DXC, py = y * DXC, pz = z * DXC;

        float gsum = 0.0f, gx = 0.0f, gy = 0.0f, gz = 0.0f;
        for (int j = 0; j < nq; j++) {
            float qj, xj, yj, zj;
            if (j < MAXQ) { qj = sq[j]; xj = sx[j]; yj = sy[j]; zj = sz[j]; }
            else          { qj = q[j]; xj = xq[3*j]; yj = xq[3*j+1]; zj = xq[3*j+2]; }
            float dx = px - xj, dy = py - yj, dz = pz - zj;
            float r2 = dx*dx + dy*dy + dz*dz;
            float r  = sqrtf(r2);
            float rr = (r == 0.0f) ? EPSF : r;
            gsum += qj / rr;
            float r3  = r2 * r;                    // r2^1.5
            float rr3 = (r3 == 0.0f) ? EPSF : r3;
            float c = -qj / rr3;
            gx += c * dx; gy += c * dy; gz += c * dz;
        }
        const float inv4pi = 1.0f / FOUR_PI_F;
        float g = gsum * inv4pi;

        float nx = normals[3*i + 0], ny = normals[3*i + 1], nz = normals[3*i + 2];
        float gcnd = (gx*nx + gy*ny + gz*nz) * inv4pi;

        // loss1: mean over (B, NB) of g^2 — batch-invariant -> per-point g^2
        acc = g * g;

        // loss2: finite differences per batch
        long base = ((long)x * NN + y) * NN + z;
        float sum2 = 0.0f;
        #pragma unroll
        for (int b = 0; b < 2; b++) {
            const float* ob = outf + (long)b * NN * NN * NN;
            float c0    = ob[base];
            float left  = ob[base - NN*NN];
            float right = ob[base + NN*NN];
            float below = ob[base - NN];
            float above = ob[base + NN];
            float back  = ob[base - 1];
            float front = ob[base + 1];
            float gxin  = (nx > 0.0f) ? (c0 - left ) * INV_DX : (right - c0) * INV_DX;
            float gxout = (nx > 0.0f) ? (right - c0) * INV_DX : (c0 - left ) * INV_DX;
            float gyin  = (ny > 0.0f) ? (c0 - below) * INV_DX : (above - c0) * INV_DX;
            float gyout = (ny > 0.0f) ? (above - c0) * INV_DX : (c0 - below) * INV_DX;
            float gzin  = (nz > 0.0f) ? (c0 - back ) * INV_DX : (front - c0) * INV_DX;
            float gzout = (nz > 0.0f) ? (front - c0) * INV_DX : (c0 - back ) * INV_DX;
            float nd_in  = gxin *nx + gyin *ny + gzin *nz;
            float nd_out = gxout*nx + gyout*ny + gzout*nz;
            float t = (nd_in + gcnd) - E_OUT_C * nd_out;   // E_IN = 1
            sum2 += t * t;
        }
        acc += 0.5f * sum2;   // 1/BATCH
    }

    // deterministic block reduction
    __shared__ float red[TPB];
    red[threadIdx.x] = acc;
    __syncthreads();
    for (int s = TPB/2; s > 0; s >>= 1) {
        if (threadIdx.x < s) red[threadIdx.x] += red[threadIdx.x + s];
        __syncthreads();
    }
    if (threadIdx.x == 0) g_partials[blockIdx.x] = red[0];
}

__global__ void finalize_kernel(float* __restrict__ outp, int nblocks, int nb)
{
    __shared__ double red[TPB];
    double a = 0.0;
    for (int i = threadIdx.x; i < nblocks; i += TPB) a += (double)g_partials[i];
    red[threadIdx.x] = a;
    __syncthreads();
    for (int s = TPB/2; s > 0; s >>= 1) {
        if (threadIdx.x < s) red[threadIdx.x] += red[threadIdx.x + s];
        __syncthreads();
    }
    if (threadIdx.x == 0) outp[0] = (float)(red[0] / (double)nb);
}

extern "C" void kernel_launch(void* const* d_in, const int* in_sizes, int n_in,
                              void* d_out, int out_size)
{
    // metadata order: output, q, xq, points, x_idx, y_idx, z_idx, normals
    const float* outf    = (const float*)d_in[0];
    const float* q       = (const float*)d_in[1];
    const float* xq      = (const float*)d_in[2];
    // d_in[3] = points (unused: recomputed from indices)
    const int*   xi      = (const int*)  d_in[4];
    const int*   yi      = (const int*)  d_in[5];
    const int*   zi      = (const int*)  d_in[6];
    const float* normals = (const float*)d_in[7];

    int nq = in_sizes[1];
    int nb = in_sizes[4];

    int blocks = (nb + TPB - 1) / TPB;
    if (blocks > MAX_BLOCKS) blocks = MAX_BLOCKS; // nb <= 262144 -> blocks <= 1024, safe

    boundary_loss_kernel<<<blocks, TPB>>>(outf, q, xq, xi, yi, zi, normals, nb, nq);
    finalize_kernel<<<1, TPB>>>((float*)d_out, blocks, nb);
}

// round 2
// speedup vs baseline: 3.8095x; 3.8095x over previous
#include <cuda_runtime.h>

// Problem constants (fixed by the reference)
#define NN        64
#define INV_DX    63.0f                 // 1/DX, DX = 1/(64-1)
#define DXC       (1.0f/63.0f)
#define E_OUT_C   80.0f                 // E_IN = 1
#define FOUR_PI_F 12.566370614359172f
#define EPSF      1.1920928955078125e-07f
#define TPB       256
#define WPB       8                     // warps per block, 1 point per warp
#define MAXQ      512                   // NQ = 200

__device__ float    g_accum = 0.0f;
__device__ unsigned g_count = 0;

__global__ void boundary_loss_fused(const float* __restrict__ outf,    // (2,1,64,64,64)
                                    const float* __restrict__ q,      // (NQ)
                                    const float* __restrict__ xq,     // (NQ,3)
                                    const int*   __restrict__ xi,
                                    const int*   __restrict__ yi,
                                    const int*   __restrict__ zi,
                                    const float* __restrict__ normals,// (NB,3)
                                    float* __restrict__ outp,
                                    int nb, int nq)
{
    __shared__ float sq[MAXQ], sx[MAXQ], sy[MAXQ], sz[MAXQ];
    __shared__ float warp_acc[WPB];

    int tid  = threadIdx.x;
    int wid  = tid >> 5;
    int lane = tid & 31;

    // stage charges in shared (conflict-free stride-1 access later)
    for (int j = tid; j < nq && j < MAXQ; j += TPB) {
        sq[j] = q[j];
        sx[j] = xq[3*j + 0];
        sy[j] = xq[3*j + 1];
        sz[j] = xq[3*j + 2];
    }
    __syncthreads();

    int i = blockIdx.x * WPB + wid;     // boundary-point index for this warp
    float acc = 0.0f;

    if (i < nb) {
        int x = xi[i], y = yi[i], z = zi[i];
        float px = x * DXC, py = y * DXC, pz = z * DXC;
        float nx = normals[3*i + 0], ny = normals[3*i + 1], nz = normals[3*i + 2];

        // ---- stencil loads (warp-uniform broadcast addresses), issued early ----
        long base = ((long)x * NN + y) * NN + z;
        const float* ob0 = outf;
        const float* ob1 = outf + (long)NN * NN * NN;
        float c0a = ob0[base],        c0b = ob1[base];
        float lfa = ob0[base-NN*NN],  lfb = ob1[base-NN*NN];
        float rta = ob0[base+NN*NN],  rtb = ob1[base+NN*NN];
        float bla = ob0[base-NN],     blb = ob1[base-NN];
        float aba = ob0[base+NN],     abb = ob1[base+NN];
        float bka = ob0[base-1],      bkb = ob1[base-1];
        float fra = ob0[base+1],      frb = ob1[base+1];

        // ---- charge loop split across lanes ----
        float gsum = 0.0f, gx = 0.0f, gy = 0.0f, gz = 0.0f;
        for (int j = lane; j < nq; j += 32) {
            float qj = sq[j];
            float dx = px - sx[j], dy = py - sy[j], dz = pz - sz[j];
            float r2 = fmaf(dx, dx, fmaf(dy, dy, dz * dz));
            if (r2 == 0.0f) {                 // exact-coincidence EPS semantics
                gsum += qj * (1.0f / EPSF);   // grad term is 0 (r_diff = 0)
            } else {
                float rinv = rsqrtf(r2);
                float qr   = qj * rinv;       // q / r
                gsum += qr;
                float c = qr * rinv * rinv;   // q / r^3
                gx = fmaf(-c, dx, gx);
                gy = fmaf(-c, dy, gy);
                gz = fmaf(-c, dz, gz);
            }
        }
        // warp butterfly reduction (all lanes end with full sums)
        #pragma unroll
        for (int s = 16; s > 0; s >>= 1) {
            gsum += __shfl_xor_sync(0xffffffffu, gsum, s);
            gx   += __shfl_xor_sync(0xffffffffu, gx,   s);
            gy   += __shfl_xor_sync(0xffffffffu, gy,   s);
            gz   += __shfl_xor_sync(0xffffffffu, gz,   s);
        }

        const float inv4pi = 1.0f / FOUR_PI_F;
        float g    = gsum * inv4pi;
        float gcnd = (gx*nx + gy*ny + gz*nz) * inv4pi;

        // loss1 term (batch-invariant): g^2
        acc = g * g;

        // loss2: finite differences, both batches (computed uniformly per warp)
        float gxinA  = (nx > 0.0f) ? (c0a - lfa) : (rta - c0a);
        float gxoutA = (nx > 0.0f) ? (rta - c0a) : (c0a - lfa);
        float gyinA  = (ny > 0.0f) ? (c0a - bla) : (aba - c0a);
        float gyoutA = (ny > 0.0f) ? (aba - c0a) : (c0a - bla);
        float gzinA  = (nz > 0.0f) ? (c0a - bka) : (fra - c0a);
        float gzoutA = (nz > 0.0f) ? (fra - c0a) : (c0a - bka);
        float ndinA  = (gxinA *nx + gyinA *ny + gzinA *nz) * INV_DX;
        float ndoutA = (gxoutA*nx + gyoutA*ny + gzoutA*nz) * INV_DX;
        float tA = (ndinA + gcnd) - E_OUT_C * ndoutA;

        float gxinB  = (nx > 0.0f) ? (c0b - lfb) : (rtb - c0b);
        float gxoutB = (nx > 0.0f) ? (rtb - c0b) : (c0b - lfb);
        float gyinB  = (ny > 0.0f) ? (c0b - blb) : (abb - c0b);
        float gyoutB = (ny > 0.0f) ? (abb - c0b) : (c0b - blb);
        float gzinB  = (nz > 0.0f) ? (c0b - bkb) : (frb - c0b);
        float gzoutB = (nz > 0.0f) ? (frb - c0b) : (c0b - bkb);
        float ndinB  = (gxinB *nx + gyinB *ny + gzinB *nz) * INV_DX;
        float ndoutB = (gxoutB*nx + gyoutB*ny + gzoutB*nz) * INV_DX;
        float tB = (ndinB + gcnd) - E_OUT_C * ndoutB;

        acc += 0.5f * (tA * tA + tB * tB);    // 1/BATCH
    }

    // ---- block reduction: one value per warp ----
    if (lane == 0) warp_acc[wid] = acc;
    __syncthreads();

    if (tid == 0) {
        float bsum = 0.0f;
        #pragma unroll
        for (int w = 0; w < WPB; w++) bsum += warp_acc[w];
        atomicAdd(&g_accum, bsum);
        __threadfence();
        unsigned old = atomicAdd(&g_count, 1u);
        if (old == gridDim.x - 1) {           // last block: finalize + reset
            float total = *(volatile float*)&g_accum;
            outp[0] = total / (float)nb;
            g_accum = 0.0f;
            __threadfence();
            g_count = 0;
        }
    }
}

extern "C" void kernel_launch(void* const* d_in, const int* in_sizes, int n_in,
                              void* d_out, int out_size)
{
    // metadata order: output, q, xq, points, x_idx, y_idx, z_idx, normals
    const float* outf    = (const float*)d_in[0];
    const float* q       = (const float*)d_in[1];
    const float* xq      = (const float*)d_in[2];
    const int*   xi      = (const int*)  d_in[4];
    const int*   yi      = (const int*)  d_in[5];
    const int*   zi      = (const int*)  d_in[6];
    const float* normals = (const float*)d_in[7];

    int nq = in_sizes[1];
    int nb = in_sizes[4];

    int blocks = (nb + WPB - 1) / WPB;

    boundary_loss_fused<<<blocks, TPB>>>(outf, q, xq, xi, yi, zi, normals,
                                         (float*)d_out, nb, nq);
}

// round 3
// speedup vs baseline: 3.8235x; 1.0037x over previous
#include <cuda_runtime.h>

// Problem constants (fixed by the reference)
#define NN        64
#define INV_DX    63.0f                 // 1/DX, DX = 1/(64-1)
#define DXC       (1.0f/63.0f)
#define E_OUT_C   80.0f                 // E_IN = 1
#define FOUR_PI_F 12.566370614359172f
#define EPSF      1.1920928955078125e-07f
#define TPB       512
#define WPB       16                    // warps per block, 1 point per warp
#define MAXQ      512                   // NQ = 200

__device__ float    g_accum = 0.0f;
__device__ unsigned g_count = 0;

__global__ __launch_bounds__(TPB)
void boundary_loss_fused(const float* __restrict__ outf,    // (2,1,64,64,64)
                         const float* __restrict__ q,      // (NQ)
                         const float* __restrict__ xq,     // (NQ,3)
                         const int*   __restrict__ xi,
                         const int*   __restrict__ yi,
                         const int*   __restrict__ zi,
                         const float* __restrict__ normals,// (NB,3)
                         float* __restrict__ outp,
                         int nb, int nq)
{
    __shared__ float4 s4[MAXQ];         // {x, y, z, q} per charge
    __shared__ float  warp_acc[WPB];

    int tid  = threadIdx.x;
    int wid  = tid >> 5;
    int lane = tid & 31;

    // stage charges packed as float4
    for (int j = tid; j < nq && j < MAXQ; j += TPB) {
        float4 v;
        v.x = xq[3*j + 0];
        v.y = xq[3*j + 1];
        v.z = xq[3*j + 2];
        v.w = q[j];
        s4[j] = v;
    }

    int i = blockIdx.x * WPB + wid;     // boundary-point index for this warp
    float acc = 0.0f;

    // issue point-descriptor loads before the barrier (independent of staging)
    int x = 0, y = 0, z = 0;
    float nx = 0.f, ny = 0.f, nz = 0.f;
    if (i < nb) {
        x  = xi[i]; y = yi[i]; z = zi[i];
        nx = normals[3*i + 0]; ny = normals[3*i + 1]; nz = normals[3*i + 2];
    }
    __syncthreads();

    if (i < nb) {
        float px = x * DXC, py = y * DXC, pz = z * DXC;

        // ---- stencil loads (warp-uniform broadcast), issued early ----
        long base = ((long)x * NN + y) * NN + z;
        const float* ob0 = outf;
        const float* ob1 = outf + (long)NN * NN * NN;
        float c0a = ob0[base],        c0b = ob1[base];
        float lfa = ob0[base-NN*NN],  lfb = ob1[base-NN*NN];
        float rta = ob0[base+NN*NN],  rtb = ob1[base+NN*NN];
        float bla = ob0[base-NN],     blb = ob1[base-NN];
        float aba = ob0[base+NN],     abb = ob1[base+NN];
        float bka = ob0[base-1],      bkb = ob1[base-1];
        float fra = ob0[base+1],      frb = ob1[base+1];

        // ---- charge loop split across lanes; normal-dot folded in ----
        float gsum = 0.0f, gnd = 0.0f;
        for (int j = lane; j < nq; j += 32) {
            float4 v = s4[j];
            float dx = px - v.x, dy = py - v.y, dz = pz - v.z;
            float r2 = fmaf(dx, dx, fmaf(dy, dy, dz * dz));
            if (r2 == 0.0f) {
                gsum += v.w * (1.0f / EPSF);   // grad term is 0 (r_diff = 0)
            } else {
                float rinv = rsqrtf(r2);
                float qr   = v.w * rinv;       // q / r
                gsum += qr;
                float c = qr * rinv * rinv;    // q / r^3
                float dot = fmaf(dx, nx, fmaf(dy, ny, dz * nz));
                gnd = fmaf(-c, dot, gnd);
            }
        }
        // warp butterfly reduction: only 2 values
        #pragma unroll
        for (int s = 16; s > 0; s >>= 1) {
            gsum += __shfl_xor_sync(0xffffffffu, gsum, s);
            gnd  += __shfl_xor_sync(0xffffffffu, gnd,  s);
        }

        const float inv4pi = 1.0f / FOUR_PI_F;
        float g    = gsum * inv4pi;
        float gcnd = gnd  * inv4pi;

        // loss1 term (batch-invariant): g^2
        acc = g * g;

        // loss2: finite differences, both batches
        float gxinA  = (nx > 0.0f) ? (c0a - lfa) : (rta - c0a);
        float gxoutA = (nx > 0.0f) ? (rta - c0a) : (c0a - lfa);
        float gyinA  = (ny > 0.0f) ? (c0a - bla) : (aba - c0a);
        float gyoutA = (ny > 0.0f) ? (aba - c0a) : (c0a - bla);
        float gzinA  = (nz > 0.0f) ? (c0a - bka) : (fra - c0a);
        float gzoutA = (nz > 0.0f) ? (fra - c0a) : (c0a - bka);
        float ndinA  = (gxinA *nx + gyinA *ny + gzinA *nz) * INV_DX;
        float ndoutA = (gxoutA*nx + gyoutA*ny + gzoutA*nz) * INV_DX;
        float tA = (ndinA + gcnd) - E_OUT_C * ndoutA;

        float gxinB  = (nx > 0.0f) ? (c0b - lfb) : (rtb - c0b);
        float gxoutB = (nx > 0.0f) ? (rtb - c0b) : (c0b - lfb);
        float gyinB  = (ny > 0.0f) ? (c0b - blb) : (abb - c0b);
        float gyoutB = (ny > 0.0f) ? (abb - c0b) : (c0b - blb);
        float gzinB  = (nz > 0.0f) ? (c0b - bkb) : (frb - c0b);
        float gzoutB = (nz > 0.0f) ? (frb - c0b) : (c0b - bkb);
        float ndinB  = (gxinB *nx + gyinB *ny + gzinB *nz) * INV_DX;
        float ndoutB = (gxoutB*nx + gyoutB*ny + gzoutB*nz) * INV_DX;
        float tB = (ndinB + gcnd) - E_OUT_C * ndoutB;

        acc += 0.5f * (tA * tA + tB * tB);    // 1/BATCH
    }

    // ---- block reduction: one value per warp ----
    if (lane == 0) warp_acc[wid] = acc;
    __syncthreads();

    if (tid == 0) {
        float bsum = 0.0f;
        #pragma unroll
        for (int w = 0; w < WPB; w++) bsum += warp_acc[w];
        atomicAdd(&g_accum, bsum);
        __threadfence();
        unsigned old = atomicAdd(&g_count, 1u);
        if (old == gridDim.x - 1) {           // last block: finalize + reset
            float total = *(volatile float*)&g_accum;
            outp[0] = total / (float)nb;
            g_accum = 0.0f;
            __threadfence();
            g_count = 0;
        }
    }
}

extern "C" void kernel_launch(void* const* d_in, const int* in_sizes, int n_in,
                              void* d_out, int out_size)
{
    // metadata order: output, q, xq, points, x_idx, y_idx, z_idx, normals
    const float* outf    = (const float*)d_in[0];
    const float* q       = (const float*)d_in[1];
    const float* xq      = (const float*)d_in[2];
    const int*   xi      = (const int*)  d_in[4];
    const int*   yi      = (const int*)  d_in[5];
    const int*   zi      = (const int*)  d_in[6];
    const float* normals = (const float*)d_in[7];

    int nq = in_sizes[1];
    int nb = in_sizes[4];

    int blocks = (nb + WPB - 1) / WPB;

    boundary_loss_fused<<<blocks, TPB>>>(outf, q, xq, xi, yi, zi, normals,
                                         (float*)d_out, nb, nq);
}